// round 4
// baseline (speedup 1.0000x reference)
#include <cuda_runtime.h>
#include <cstdint>

#define B_    256
#define T_    512
#define DIN_  32
#define H_    128
#define G_    512
#define LAT_  64

#define SCALE_F 3.814697265625e-6f   // 2^-18
#define CC_F    32.125f              // (2^23 + 32768) * 2^-18

// smem byte offsets for scan kernel
#define OFF_HB   139264              // 512 rows * 136 u16 * 2B
#define OFF_GB   140288
#define OFF_PART 144384
#define SMEM_SZ  144448

typedef unsigned long long u64t;

// ---------------- device scratch ----------------
__device__ float          g_xg[(size_t)B_ * T_ * G_];     // encoder input gates
__device__ float          g_xgdec[B_ * G_];               // decoder input gates (const over t)
__device__ float          g_hs2[(size_t)B_ * T_ * H_];    // decoder hidden states
__device__ unsigned short g_w16[2 * G_ * H_];

// ---------------- helpers ----------------
__device__ __forceinline__ float sigf(float x) {
    return __fdividef(1.0f, 1.0f + __expf(-x));
}
__device__ __forceinline__ float tanh_fast(float x) {
    return __fdividef(2.0f, 1.0f + __expf(-2.0f * x)) - 1.0f;
}
__device__ __forceinline__ void ffma2(u64t& acc, u64t a, u64t b) {
    asm("fma.rn.f32x2 %0, %1, %2, %0;" : "+l"(acc) : "l"(a), "l"(b));
}
__device__ __forceinline__ float red2(u64t a) {
    float lo, hi;
    asm("mov.b64 {%0,%1}, %2;" : "=f"(lo), "=f"(hi) : "l"(a));
    return lo + hi;
}
// build {float(2^23+u16lo), float(2^23+u16hi)} from packed u32
__device__ __forceinline__ u64t wpair(unsigned w) {
    u64t r;
    asm("{\n\t"
        ".reg .b32 lo, hi;\n\t"
        "prmt.b32 lo, %1, 0x4B000000, 0x7410;\n\t"
        "prmt.b32 hi, %1, 0x4B000000, 0x7432;\n\t"
        "mov.b64 %0, {lo, hi};\n\t"
        "}" : "=l"(r) : "r"(w));
    return r;
}

// ---------------- weight prep ----------------
__global__ void prep_w_kernel(const float* __restrict__ encW,
                              const float* __restrict__ decW) {
    int i = blockIdx.x * blockDim.x + threadIdx.x;   // 0..65535
    int k = i & 127;
    float qe = rintf(encW[i] * 262144.0f);
    float qd = rintf(decW[i] * 262144.0f);
    float me = (k & 1) ? (32768.0f - qe) : (32768.0f + qe);
    float md = (k & 1) ? (32768.0f - qd) : (32768.0f + qd);
    g_w16[i]           = (unsigned short)(int)me;
    g_w16[G_ * H_ + i] = (unsigned short)(int)md;
}

// ---------------- xg_enc = x @ enc_Wih.T + bih + bhh ----------------
__global__ void __launch_bounds__(512) xg_enc_kernel(
    const float* __restrict__ x, const float* __restrict__ Wih,
    const float* __restrict__ bih, const float* __restrict__ bhh) {
    __shared__ float xs[512];
    int b  = blockIdx.x >> 5;
    int t0 = (blockIdx.x & 31) << 4;
    int tid = threadIdx.x;
    xs[tid] = x[((size_t)b * T_ + t0) * DIN_ + tid];
    int g = tid;
    float bias = bih[g] + bhh[g];
    float4 w[8];
    const float4* W4 = (const float4*)(Wih + g * DIN_);
#pragma unroll
    for (int i = 0; i < 8; i++) w[i] = W4[i];
    __syncthreads();
#pragma unroll 1
    for (int tt = 0; tt < 16; tt++) {
        const float4* xv = (const float4*)(xs + tt * 32);
        float a0 = bias, a1 = 0.0f;
#pragma unroll
        for (int i = 0; i < 8; i += 2) {
            float4 wa = w[i], ha = xv[i];
            a0 = fmaf(wa.x, ha.x, a0); a0 = fmaf(wa.y, ha.y, a0);
            a0 = fmaf(wa.z, ha.z, a0); a0 = fmaf(wa.w, ha.w, a0);
            float4 wb = w[i + 1], hb = xv[i + 1];
            a1 = fmaf(wb.x, hb.x, a1); a1 = fmaf(wb.y, hb.y, a1);
            a1 = fmaf(wb.z, hb.z, a1); a1 = fmaf(wb.w, hb.w, a1);
        }
        g_xg[((size_t)(b * T_ + t0 + tt)) * G_ + g] = a0 + a1;
    }
}

// ---------------- xg_dec = encoded @ dec_Wih.T + bih + bhh (standalone) ----------------
__global__ void __launch_bounds__(512) xg_dec_kernel(
    const float* __restrict__ enc, const float* __restrict__ Wih,
    const float* __restrict__ bih, const float* __restrict__ bhh) {
    __shared__ float es[LAT_];
    int b = blockIdx.x, tid = threadIdx.x;
    if (tid < LAT_) es[tid] = enc[b * LAT_ + tid];
    __syncthreads();
    int g = tid;
    float a0 = bih[g] + bhh[g], a1 = 0.0f;
    const float4* W4 = (const float4*)(Wih + g * LAT_);
    const float4* ev = (const float4*)es;
#pragma unroll
    for (int i = 0; i < 16; i += 2) {
        float4 wa = W4[i], ea = ev[i];
        a0 = fmaf(wa.x, ea.x, a0); a0 = fmaf(wa.y, ea.y, a0);
        a0 = fmaf(wa.z, ea.z, a0); a0 = fmaf(wa.w, ea.w, a0);
        float4 wb = W4[i + 1], eb = ev[i + 1];
        a1 = fmaf(wb.x, eb.x, a1); a1 = fmaf(wb.y, eb.y, a1);
        a1 = fmaf(wb.z, eb.z, a1); a1 = fmaf(wb.w, eb.w, a1);
    }
    g_xgdec[b * G_ + g] = a0 + a1;
}

// ---------------- persistent LSTM scan: 128 CTAs x 2 batch rows ----------------
template <int IS_DEC>
__global__ void __launch_bounds__(512, 1) scan_kernel(
    const float* __restrict__ Wl, const float* __restrict__ bl,
    float* __restrict__ out) {
    extern __shared__ char sm[];
    unsigned short* wsh = (unsigned short*)sm;
    float* hb0  = (float*)(sm + OFF_HB);
    float* hb1  = hb0 + 128;
    float* gb   = (float*)(sm + OFF_GB);
    float* part = (float*)(sm + OFF_PART);

    const int tid = threadIdx.x;
    const int g   = tid;
    const int r0  = blockIdx.x * 2;

    // copy packed weights: 128 u16 per row -> smem stride 136 u16 (17 uint4)
    {
        const uint4* src = (const uint4*)(g_w16 + (IS_DEC ? G_ * H_ : 0) + g * H_);
        uint4* dst = (uint4*)wsh + g * 17;
#pragma unroll
        for (int i = 0; i < 16; i++) dst[i] = src[i];
    }
    if (tid < 64) ((float4*)hb0)[tid] = make_float4(0.f, 0.f, 0.f, 0.f);
    if (tid >= 64 && tid < 72) part[tid - 64] = 0.0f;
    __syncthreads();

    float c0 = 0.0f;      // cell state for threads < 256
    float x0, x1;
    const float *xp0 = nullptr, *xp1 = nullptr;
    if (!IS_DEC) {
        xp0 = g_xg + ((size_t)(r0 * T_)) * G_ + g;
        xp1 = g_xg + ((size_t)((r0 + 1) * T_)) * G_ + g;
        x0 = __ldg(xp0); x1 = __ldg(xp1);
    } else {
        x0 = g_xgdec[(size_t)r0 * G_ + g];
        x1 = g_xgdec[(size_t)(r0 + 1) * G_ + g];
    }

    const uint4* wrow = (const uint4*)wsh + g * 17;
    const u64t* h0u = (const u64t*)hb0;
    const u64t* h1u = (const u64t*)hb1;

#pragma unroll 1
    for (int t = 0; t < T_; t++) {
        u64t a0c[4] = {0, 0, 0, 0};
        u64t a1c[4] = {0, 0, 0, 0};
#pragma unroll
        for (int i = 0; i < 16; i++) {
            uint4 wv = wrow[i];
            u64t w01 = wpair(wv.x), w23 = wpair(wv.y);
            u64t w45 = wpair(wv.z), w67 = wpair(wv.w);
            u64t p00 = h0u[4 * i + 0], p01 = h0u[4 * i + 1];
            u64t p02 = h0u[4 * i + 2], p03 = h0u[4 * i + 3];
            u64t p10 = h1u[4 * i + 0], p11 = h1u[4 * i + 1];
            u64t p12 = h1u[4 * i + 2], p13 = h1u[4 * i + 3];
            const int c = i >> 2;
            ffma2(a0c[c], w01, p00); ffma2(a1c[c], w01, p10);
            ffma2(a0c[c], w23, p01); ffma2(a1c[c], w23, p11);
            ffma2(a0c[c], w45, p02); ffma2(a1c[c], w45, p12);
            ffma2(a0c[c], w67, p03); ffma2(a1c[c], w67, p13);
        }
        float4 p0 = ((const float4*)part)[0];
        float4 p1 = ((const float4*)part)[1];
        float g0 = x0, g1 = x1;
        g0 += fmaf(red2(a0c[0]), SCALE_F, -CC_F * p0.x);
        g0 += fmaf(red2(a0c[1]), SCALE_F, -CC_F * p0.y);
        g0 += fmaf(red2(a0c[2]), SCALE_F, -CC_F * p0.z);
        g0 += fmaf(red2(a0c[3]), SCALE_F, -CC_F * p0.w);
        g1 += fmaf(red2(a1c[0]), SCALE_F, -CC_F * p1.x);
        g1 += fmaf(red2(a1c[1]), SCALE_F, -CC_F * p1.y);
        g1 += fmaf(red2(a1c[2]), SCALE_F, -CC_F * p1.z);
        g1 += fmaf(red2(a1c[3]), SCALE_F, -CC_F * p1.w);
        gb[g]      = g0;
        gb[G_ + g] = g1;
        if (!IS_DEC && t + 1 < T_) {   // prefetch next step's input gates
            x0 = __ldg(xp0 + (size_t)(t + 1) * G_);
            x1 = __ldg(xp1 + (size_t)(t + 1) * G_);
        }
        __syncthreads();   // A: gates ready
        if (tid < 256) {
            int r = tid >> 7, j = tid & 127;
            const float* gr = gb + r * G_;
            float gi = sigf(gr[j]);
            float gf = sigf(gr[j + 128]);
            float gg = tanh_fast(gr[j + 256]);
            float go = sigf(gr[j + 384]);
            float c = fmaf(gf, c0, gi * gg);
            c0 = c;
            float h = go * tanh_fast(c);
            float hs = (j & 1) ? -h : h;          // fold alternating sign
            (r ? hb1 : hb0)[j] = hs;
            if (IS_DEC)
                g_hs2[((size_t)((r0 + r) * T_ + t)) * H_ + j] = h;
            float sv = hs;
#pragma unroll
            for (int o = 16; o; o >>= 1) sv += __shfl_xor_sync(0xffffffffu, sv, o);
            if ((tid & 31) == 0) part[r * 4 + ((tid >> 5) & 3)] = sv;
        }
        __syncthreads();   // B: h/part ready
    }

    if (!IS_DEC && tid < 128) {        // encoded = h_last @ enc_Wl.T + enc_bl
        int r = tid >> 6, o = tid & 63;
        const float4* W4 = (const float4*)(Wl + o * H_);
        const float* hbr = r ? hb1 : hb0;
        float acc = bl[o], acc2 = 0.0f;
#pragma unroll
        for (int k4 = 0; k4 < 32; k4++) {
            float4 w = W4[k4];
            int k = 4 * k4;
            acc  = fmaf(w.x,  hbr[k],     acc);   // even k: hb = +h
            acc2 = fmaf(w.y, -hbr[k + 1], acc2);  // odd k: true h = -hb
            acc  = fmaf(w.z,  hbr[k + 2], acc);
            acc2 = fmaf(w.w, -hbr[k + 3], acc2);
        }
        out[(r0 + r) * LAT_ + o] = acc + acc2;
    }
}

// ---------------- decoded = hs2 @ dec_Wl.T + dec_bl (simple & safe) ----------------
__global__ void __launch_bounds__(256) decoded_kernel(
    const float* __restrict__ Wl, const float* __restrict__ bl,
    float* __restrict__ out) {
    __shared__ float hs[8 * 128];
    int tid = threadIdx.x;
    int bt0 = blockIdx.x * 8;
    ((float4*)hs)[tid] = ((const float4*)(g_hs2 + (size_t)bt0 * H_))[tid];
    __syncthreads();
    int d = tid & 31, rl = tid >> 5;
    const float4* wv = (const float4*)(Wl + d * H_);
    const float4* hv = (const float4*)(hs + rl * H_);
    float a0 = bl[d], a1 = 0.0f;
#pragma unroll
    for (int k4 = 0; k4 < 32; k4 += 2) {
        float4 w = wv[k4], h = hv[k4];
        a0 = fmaf(w.x, h.x, a0); a0 = fmaf(w.y, h.y, a0);
        a0 = fmaf(w.z, h.z, a0); a0 = fmaf(w.w, h.w, a0);
        float4 w2 = wv[k4 + 1], h2 = hv[k4 + 1];
        a1 = fmaf(w2.x, h2.x, a1); a1 = fmaf(w2.y, h2.y, a1);
        a1 = fmaf(w2.z, h2.z, a1); a1 = fmaf(w2.w, h2.w, a1);
    }
    size_t base = (size_t)B_ * LAT_;   // decoded starts after encoded
    out[base + (size_t)(bt0 + rl) * DIN_ + d] = a0 + a1;
}

// ---------------- launch ----------------
extern "C" void kernel_launch(void* const* d_in, const int* in_sizes, int n_in,
                              void* d_out, int out_size) {
    const float* x    = (const float*)d_in[0];
    const float* eWih = (const float*)d_in[1];
    const float* eWhh = (const float*)d_in[2];
    const float* ebih = (const float*)d_in[3];
    const float* ebhh = (const float*)d_in[4];
    const float* eWl  = (const float*)d_in[5];
    const float* ebl  = (const float*)d_in[6];
    const float* dWih = (const float*)d_in[7];
    const float* dWhh = (const float*)d_in[8];
    const float* dbih = (const float*)d_in[9];
    const float* dbhh = (const float*)d_in[10];
    const float* dWl  = (const float*)d_in[11];
    const float* dbl  = (const float*)d_in[12];
    float* out = (float*)d_out;

    cudaFuncSetAttribute(scan_kernel<0>,
                         cudaFuncAttributeMaxDynamicSharedMemorySize, SMEM_SZ);
    cudaFuncSetAttribute(scan_kernel<1>,
                         cudaFuncAttributeMaxDynamicSharedMemorySize, SMEM_SZ);

    prep_w_kernel<<<256, 256>>>(eWhh, dWhh);
    xg_enc_kernel<<<B_ * 32, 512>>>(x, eWih, ebih, ebhh);
    scan_kernel<0><<<B_ / 2, 512, SMEM_SZ>>>(eWl, ebl, out);
    xg_dec_kernel<<<B_, 512>>>(out, dWih, dbih, dbhh);
    scan_kernel<1><<<B_ / 2, 512, SMEM_SZ>>>(dWl, dbl, out);
    decoded_kernel<<<(B_ * T_) / 8, 256>>>(dWl, dbl, out);
}